// round 1
// baseline (speedup 1.0000x reference)
#include <cuda_runtime.h>

#define PACT 484      // 22*22 active pixels
#define NM   22
#define NB   32
#define CCH  256

// Scratch (static device allocations - allowed)
__device__ float g_qkva[(size_t)NB * 768 * PACT];          // qp | k | v at active pixels
__device__ float g_oscr[(size_t)NB * 4 * 64 * 1600];       // o patches [n][h][d][s(100)][l(16)]
__device__ float g_folded[(size_t)NB * CCH * PACT];        // folded at active pixels

// ---------------------------------------------------------------------------
// Fill the whole output with the projection bias (inactive pixels = bias only)
// ---------------------------------------------------------------------------
__global__ __launch_bounds__(256) void fill_bias(float* __restrict__ out,
                                                 const float* __restrict__ b_proj) {
    size_t i4 = (size_t)blockIdx.x * 256 + threadIdx.x;   // float4 index
    // total floats = 32*256*4096 = 33554432 -> 8388608 float4
    if (i4 < 8388608u) {
        int ch = (int)((i4 >> 10) & 255);
        float bv = b_proj[ch];
        ((float4*)out)[i4] = make_float4(bv, bv, bv, bv);
    }
}

// ---------------------------------------------------------------------------
// GEMM1: per batch n, OUT(768,484) = [w_q; w_kv](768,256) @ Xa(256,484) + bias
// Xa gathered from q at active pixels (3m, 3m2).
// Tile 128x128, K-step 8, 256 threads, 8x8 micro-tile (split 4+4 mapping).
// ---------------------------------------------------------------------------
__global__ __launch_bounds__(256) void gemm_qkv(const float* __restrict__ q,
                                                const float* __restrict__ w_q,
                                                const float* __restrict__ b_q,
                                                const float* __restrict__ w_kv,
                                                const float* __restrict__ b_kv) {
    const int n  = blockIdx.z;
    const int o0 = blockIdx.y * 128;
    const int p0 = blockIdx.x * 128;

    const float* W;
    const float* bias;
    int orow0;
    if (o0 < 256) { W = w_q;  bias = b_q;  orow0 = o0; }
    else          { W = w_kv; bias = b_kv; orow0 = o0 - 256; }

    __shared__ float As[8][128];   // As[k][row]
    __shared__ float Bs[8][128];   // Bs[k][col]

    const int tid = threadIdx.x;
    const int tx = tid & 15;       // col group
    const int ty = tid >> 4;       // row group

    float acc[8][8];
#pragma unroll
    for (int i = 0; i < 8; i++)
#pragma unroll
        for (int j = 0; j < 8; j++) acc[i][j] = 0.f;

    const float* qn = q + (size_t)n * 256 * 4096;

    const int arow = tid >> 1;     // 0..127
    const int ac4  = tid & 1;      // which float4 in the 8-wide K slice

    for (int k0 = 0; k0 < 256; k0 += 8) {
        // A: 128 rows x 8 k, via one float4 per thread, stored transposed
        {
            float4 wv = *(const float4*)&W[(size_t)(orow0 + arow) * 256 + k0 + ac4 * 4];
            As[ac4 * 4 + 0][arow] = wv.x;
            As[ac4 * 4 + 1][arow] = wv.y;
            As[ac4 * 4 + 2][arow] = wv.z;
            As[ac4 * 4 + 3][arow] = wv.w;
        }
        // B: 8 k x 128 cols, gathered from q at (3m, 3m2)
#pragma unroll
        for (int e = 0; e < 4; e++) {
            int idx = tid + e * 256;
            int kk = idx >> 7, pl = idx & 127;
            int p = p0 + pl;
            float v = 0.f;
            if (p < PACT) {
                int m  = p / 22;
                int m2 = p - m * 22;
                v = qn[(size_t)(k0 + kk) * 4096 + m * 192 + m2 * 3];
            }
            Bs[kk][pl] = v;
        }
        __syncthreads();

#pragma unroll
        for (int kk = 0; kk < 8; kk++) {
            float4 a0 = *(const float4*)&As[kk][ty * 4];
            float4 a1 = *(const float4*)&As[kk][64 + ty * 4];
            float4 b0 = *(const float4*)&Bs[kk][tx * 4];
            float4 b1 = *(const float4*)&Bs[kk][64 + tx * 4];
            float ra[8] = {a0.x, a0.y, a0.z, a0.w, a1.x, a1.y, a1.z, a1.w};
            float rb[8] = {b0.x, b0.y, b0.z, b0.w, b1.x, b1.y, b1.z, b1.w};
#pragma unroll
            for (int i = 0; i < 8; i++)
#pragma unroll
                for (int j = 0; j < 8; j++) acc[i][j] += ra[i] * rb[j];
        }
        __syncthreads();
    }

    float* outb = g_qkva + (size_t)n * 768 * PACT;
#pragma unroll
    for (int i = 0; i < 8; i++) {
        int rloc = (i < 4) ? (ty * 4 + i) : (64 + ty * 4 + i - 4);
        int o = o0 + rloc;
        float bv = bias[orow0 + rloc];
#pragma unroll
        for (int j = 0; j < 8; j++) {
            int cloc = (j < 4) ? (tx * 4 + j) : (64 + tx * 4 + j - 4);
            int p = p0 + cloc;
            if (p < PACT) outb[(size_t)o * PACT + p] = acc[i][j] + bv;
        }
    }
}

// ---------------------------------------------------------------------------
// Attention: one block per (n, h, s). hd=64, L=16.
// ---------------------------------------------------------------------------
__global__ __launch_bounds__(256) void attn_kernel() {
    const int s = blockIdx.x;          // 0..99
    const int h = blockIdx.y;          // 0..3
    const int n = blockIdx.z;          // 0..31
    const int i  = s / 10;
    const int i2 = s - i * 10;

    __shared__ float qs[64][16];
    __shared__ float ks[64][16];
    __shared__ float vs[64][16];
    __shared__ float sc[16][17];

    const int tid = threadIdx.x;
    const float* base = g_qkva + (size_t)n * 768 * PACT + (size_t)h * 64 * PACT;

    for (int t = tid; t < 1024; t += 256) {
        int d = t >> 4, l = t & 15;
        int j = l >> 2, j2 = l & 3;
        int p = (2 * i + j) * 22 + (2 * i2 + j2);
        size_t off = (size_t)d * PACT + p;
        qs[d][l] = base[off];
        ks[d][l] = base[off + (size_t)256 * PACT];
        vs[d][l] = base[off + (size_t)512 * PACT];
    }
    __syncthreads();

    const int x = tid >> 4, y = tid & 15;
    float sacc = 0.f;
#pragma unroll 16
    for (int d = 0; d < 64; d++) sacc += qs[d][x] * ks[d][y];
    sacc *= 0.125f;   // hd^-0.5
    sc[x][y] = sacc;
    __syncthreads();

    float mx = -1e30f;
#pragma unroll
    for (int yy = 0; yy < 16; yy++) mx = fmaxf(mx, sc[x][yy]);
    float e = __expf(sacc - mx);
    __syncthreads();
    sc[x][y] = e;
    __syncthreads();
    float sum = 0.f;
#pragma unroll
    for (int yy = 0; yy < 16; yy++) sum += sc[x][yy];
    float attn = e / sum;
    __syncthreads();
    sc[x][y] = attn;
    __syncthreads();

    // o[d][x] = sum_y attn[x][y] * v[d][y]
    const int dg = tid >> 4;   // 0..15
    const int xx = tid & 15;
    float* ob = g_oscr + ((size_t)(n * 4 + h) * 64) * 1600 + (size_t)s * 16;
#pragma unroll
    for (int dd = 0; dd < 4; dd++) {
        int d = dg * 4 + dd;
        float o = 0.f;
#pragma unroll
        for (int yy = 0; yy < 16; yy++) o += sc[xx][yy] * vs[d][yy];
        ob[(size_t)d * 1600 + xx] = o;
    }
}

// ---------------------------------------------------------------------------
// Fold (gather, deterministic): folded[n][c][p] = sum over covering patches
// ---------------------------------------------------------------------------
__global__ __launch_bounds__(256) void fold_kernel() {
    int idx = blockIdx.x * 256 + threadIdx.x;
    const int total = NB * CCH * PACT;
    if (idx >= total) return;
    int p  = idx % PACT;
    int nc = idx / PACT;
    int c = nc & 255;
    int n = nc >> 8;
    int m  = p / 22;
    int m2 = p - m * 22;
    int h = c >> 6, d = c & 63;
    const float* ob = g_oscr + (size_t)((n * 4 + h) * 64 + d) * 1600;
    float acc = 0.f;
    for (int ja = (m & 1); ja < 4; ja += 2) {
        int ia2 = m - ja;
        if (ia2 < 0 || ia2 > 18) continue;
        int ia = ia2 >> 1;
        for (int jb = (m2 & 1); jb < 4; jb += 2) {
            int ib2 = m2 - jb;
            if (ib2 < 0 || ib2 > 18) continue;
            int ib = ib2 >> 1;
            acc += ob[(ia * 10 + ib) * 16 + ja * 4 + jb];
        }
    }
    g_folded[idx] = acc;
}

// ---------------------------------------------------------------------------
// GEMM2: per batch, OUT(256, 484) = w_proj(256,256) @ folded(256,484) + b_proj
// Scatter epilogue into the full image at (3m, 3m2).
// ---------------------------------------------------------------------------
__global__ __launch_bounds__(256) void gemm_proj(const float* __restrict__ w_proj,
                                                 const float* __restrict__ b_proj,
                                                 float* __restrict__ out) {
    const int n  = blockIdx.z;
    const int o0 = blockIdx.y * 128;
    const int p0 = blockIdx.x * 128;

    __shared__ float As[8][128];
    __shared__ float Bs[8][128];

    const int tid = threadIdx.x;
    const int tx = tid & 15;
    const int ty = tid >> 4;

    float acc[8][8];
#pragma unroll
    for (int i = 0; i < 8; i++)
#pragma unroll
        for (int j = 0; j < 8; j++) acc[i][j] = 0.f;

    const float* Bn = g_folded + (size_t)n * 256 * PACT;
    const int arow = tid >> 1;
    const int ac4  = tid & 1;

    for (int k0 = 0; k0 < 256; k0 += 8) {
        {
            float4 wv = *(const float4*)&w_proj[(size_t)(o0 + arow) * 256 + k0 + ac4 * 4];
            As[ac4 * 4 + 0][arow] = wv.x;
            As[ac4 * 4 + 1][arow] = wv.y;
            As[ac4 * 4 + 2][arow] = wv.z;
            As[ac4 * 4 + 3][arow] = wv.w;
        }
#pragma unroll
        for (int e = 0; e < 4; e++) {
            int idx = tid + e * 256;
            int kk = idx >> 7, pl = idx & 127;
            int p = p0 + pl;
            Bs[kk][pl] = (p < PACT) ? Bn[(size_t)(k0 + kk) * PACT + p] : 0.f;
        }
        __syncthreads();
#pragma unroll
        for (int kk = 0; kk < 8; kk++) {
            float4 a0 = *(const float4*)&As[kk][ty * 4];
            float4 a1 = *(const float4*)&As[kk][64 + ty * 4];
            float4 b0 = *(const float4*)&Bs[kk][tx * 4];
            float4 b1 = *(const float4*)&Bs[kk][64 + tx * 4];
            float ra[8] = {a0.x, a0.y, a0.z, a0.w, a1.x, a1.y, a1.z, a1.w};
            float rb[8] = {b0.x, b0.y, b0.z, b0.w, b1.x, b1.y, b1.z, b1.w};
#pragma unroll
            for (int i = 0; i < 8; i++)
#pragma unroll
                for (int j = 0; j < 8; j++) acc[i][j] += ra[i] * rb[j];
        }
        __syncthreads();
    }

    float* outn = out + (size_t)n * 256 * 4096;
#pragma unroll
    for (int i = 0; i < 8; i++) {
        int rloc = (i < 4) ? (ty * 4 + i) : (64 + ty * 4 + i - 4);
        int o = o0 + rloc;
        float bv = b_proj[o];
#pragma unroll
        for (int j = 0; j < 8; j++) {
            int cloc = (j < 4) ? (tx * 4 + j) : (64 + tx * 4 + j - 4);
            int p = p0 + cloc;
            if (p < PACT) {
                int m  = p / 22;
                int m2 = p - m * 22;
                outn[(size_t)o * 4096 + m * 192 + m2 * 3] = acc[i][j] + bv;
            }
        }
    }
}

extern "C" void kernel_launch(void* const* d_in, const int* in_sizes, int n_in,
                              void* d_out, int out_size) {
    const float* q      = (const float*)d_in[0];
    const float* w_q    = (const float*)d_in[1];
    const float* b_q    = (const float*)d_in[2];
    const float* w_kv   = (const float*)d_in[3];
    const float* b_kv   = (const float*)d_in[4];
    const float* w_proj = (const float*)d_in[5];
    const float* b_proj = (const float*)d_in[6];
    float* out = (float*)d_out;

    fill_bias<<<32768, 256>>>(out, b_proj);
    gemm_qkv<<<dim3(4, 6, NB), 256>>>(q, w_q, b_q, w_kv, b_kv);
    attn_kernel<<<dim3(100, 4, NB), 256>>>();
    fold_kernel<<<dim3((NB * CCH * PACT + 255) / 256), 256>>>();
    gemm_proj<<<dim3(4, 2, NB), 256>>>(w_proj, b_proj, out);
}

// round 2
// speedup vs baseline: 1.5242x; 1.5242x over previous
#include <cuda_runtime.h>
#include <cstdint>

#define PACT 484      // 22*22 active pixels
#define NB   32

// Scratch (static device allocations - allowed)
__device__ float    g_qkva [(size_t)NB * 768 * PACT];   // qp | k | v at active pixels
__device__ float    g_oscr [(size_t)NB * 4 * 64 * 1600];// o patches [n][h][d][s(100)][l(16)]
__device__ float    g_folded[(size_t)NB * 256 * PACT];  // folded at active pixels
__device__ float    g_pout [(size_t)NB * 256 * PACT];   // proj output at active pixels
__device__ unsigned g_wfrag1[48 * 32 * 128];            // [w_q;w_kv] tf32 fragments
__device__ unsigned g_wfrag2[16 * 32 * 128];            // w_proj tf32 fragments
__device__ float    g_bias768[768];

__device__ __forceinline__ unsigned f2tf(float f) {
    unsigned r; asm("cvt.rna.tf32.f32 %0, %1;" : "=r"(r) : "f"(f)); return r;
}

__device__ __forceinline__ void mma_tf32(float* d, const unsigned* a, unsigned b0, unsigned b1) {
    asm("mma.sync.aligned.m16n8k8.row.col.f32.tf32.tf32.f32 "
        "{%0,%1,%2,%3},{%4,%5,%6,%7},{%8,%9},{%0,%1,%2,%3};\n"
        : "+f"(d[0]), "+f"(d[1]), "+f"(d[2]), "+f"(d[3])
        : "r"(a[0]), "r"(a[1]), "r"(a[2]), "r"(a[3]), "r"(b0), "r"(b1));
}

// ---------------------------------------------------------------------------
// Prep: convert weights into mma-fragment-native tf32 layout, concat biases.
// wfrag[mt][ks][lane*4 + {a0,a1,a2,a3}]
// a0=(gid, ctid) a1=(gid+8, ctid) a2=(gid, ctid+4) a3=(gid+8, ctid+4)
// ---------------------------------------------------------------------------
__global__ __launch_bounds__(256) void prep_kernel(const float* __restrict__ w_q,
                                                   const float* __restrict__ b_q,
                                                   const float* __restrict__ w_kv,
                                                   const float* __restrict__ b_kv,
                                                   const float* __restrict__ w_proj) {
    int t = blockIdx.x * 256 + threadIdx.x;
    if (t < 49152) {                      // 48 mt * 32 ks * 32 lanes
        int lane = t & 31, ks = (t >> 5) & 31, mtg = t >> 10;
        int gid = lane >> 2, ctid = lane & 3;
        int r0 = mtg * 16 + gid, r1 = r0 + 8;
        int k0 = ks * 8 + ctid, k1 = k0 + 4;
        const float* W; int rb;
        if (r0 < 256) { W = w_q; rb = 0; } else { W = w_kv; rb = 256; }
        uint4 v = make_uint4(f2tf(W[(size_t)(r0 - rb) * 256 + k0]),
                             f2tf(W[(size_t)(r1 - rb) * 256 + k0]),
                             f2tf(W[(size_t)(r0 - rb) * 256 + k1]),
                             f2tf(W[(size_t)(r1 - rb) * 256 + k1]));
        ((uint4*)g_wfrag1)[t] = v;
    } else if (t < 49152 + 16384) {       // 16 mt * 32 ks * 32 lanes
        int u = t - 49152;
        int lane = u & 31, ks = (u >> 5) & 31, mtg = u >> 10;
        int gid = lane >> 2, ctid = lane & 3;
        int r0 = mtg * 16 + gid, r1 = r0 + 8;
        int k0 = ks * 8 + ctid, k1 = k0 + 4;
        uint4 v = make_uint4(f2tf(w_proj[(size_t)r0 * 256 + k0]),
                             f2tf(w_proj[(size_t)r1 * 256 + k0]),
                             f2tf(w_proj[(size_t)r0 * 256 + k1]),
                             f2tf(w_proj[(size_t)r1 * 256 + k1]));
        ((uint4*)g_wfrag2)[u] = v;
    } else if (t < 49152 + 16384 + 768) {
        int o = t - 49152 - 16384;
        g_bias768[o] = (o < 256) ? b_q[o] : b_kv[o - 256];
    }
}

// ---------------------------------------------------------------------------
// TF32 tensor-core GEMM1: per n, OUT(768,484) = [w_q;w_kv] @ gather(q) + bias
// 128x128 tile, BK=16, 8 warps (4m x 2n), warp = 32x64, m16n8k8.
// B staged in fragment-native smem layout: Bs[ks][nt][gid*8+ctid*2+half]
// ---------------------------------------------------------------------------
__global__ __launch_bounds__(256, 2) void gemm_qkv_tc(const float* __restrict__ q) {
    __shared__ unsigned Bs[2][2][16][128];   // 32 KB
    const int n = blockIdx.z, o0 = blockIdx.y * 128, p0 = blockIdx.x * 128;
    const int tid = threadIdx.x, lane = tid & 31, wid = tid >> 5;
    const int warp_m = wid >> 1, warp_n = wid & 1;
    const int gid = lane >> 2, ctid = lane & 3;
    const float* qn = q + (size_t)n * 256 * 4096;

    float acc[2][8][4] = {};

    auto stage = [&](int iter) {
        int buf = iter & 1, k0 = iter * 16;
#pragma unroll
        for (int j = 0; j < 8; j++) {
            int e = tid + j * 256;
            int col = e & 127, kk = e >> 7;
            int p = p0 + col;
            float v = 0.f;
            if (p < PACT) {
                int m = p / 22, m2 = p - m * 22;
                v = qn[(size_t)(k0 + kk) * 4096 + m * 192 + m2 * 3];
            }
            Bs[buf][kk >> 3][col >> 3][(col & 7) * 8 + (kk & 3) * 2 + ((kk >> 2) & 1)] = f2tf(v);
        }
    };
    stage(0);
    __syncthreads();

    const int mtg0 = (o0 >> 4) + warp_m * 2;
    for (int iter = 0; iter < 16; iter++) {
        if (iter + 1 < 16) stage(iter + 1);
        int buf = iter & 1;
#pragma unroll
        for (int ks = 0; ks < 2; ks++) {
            int ksg = iter * 2 + ks;
            unsigned a[2][4];
#pragma unroll
            for (int mt = 0; mt < 2; mt++) {
                uint4 av = ((const uint4*)g_wfrag1)[((mtg0 + mt) * 32 + ksg) * 32 + lane];
                a[mt][0] = av.x; a[mt][1] = av.y; a[mt][2] = av.z; a[mt][3] = av.w;
            }
#pragma unroll
            for (int nt = 0; nt < 8; nt++) {
                const unsigned* bp = &Bs[buf][ks][warp_n * 8 + nt][lane * 2];
                unsigned b0 = bp[0], b1 = bp[1];
                mma_tf32(acc[0][nt], a[0], b0, b1);
                mma_tf32(acc[1][nt], a[1], b0, b1);
            }
        }
        __syncthreads();
    }

    float* outb = g_qkva + (size_t)n * 768 * PACT;
#pragma unroll
    for (int mt = 0; mt < 2; mt++) {
        int row0 = o0 + warp_m * 32 + mt * 16 + gid;
#pragma unroll
        for (int half = 0; half < 2; half++) {
            int o = row0 + half * 8;
            float bv = g_bias768[o];
#pragma unroll
            for (int nt = 0; nt < 8; nt++) {
                int col = p0 + warp_n * 64 + nt * 8 + ctid * 2;
                if (col < PACT)     outb[(size_t)o * PACT + col]     = acc[mt][nt][half * 2 + 0] + bv;
                if (col + 1 < PACT) outb[(size_t)o * PACT + col + 1] = acc[mt][nt][half * 2 + 1] + bv;
            }
        }
    }
}

// ---------------------------------------------------------------------------
// TF32 tensor-core GEMM2: per n, POUT(256,484) = w_proj @ folded + b_proj
// ---------------------------------------------------------------------------
__global__ __launch_bounds__(256, 2) void gemm_proj_tc(const float* __restrict__ b_proj) {
    __shared__ unsigned Bs[2][2][16][128];
    const int n = blockIdx.z, o0 = blockIdx.y * 128, p0 = blockIdx.x * 128;
    const int tid = threadIdx.x, lane = tid & 31, wid = tid >> 5;
    const int warp_m = wid >> 1, warp_n = wid & 1;
    const int gid = lane >> 2, ctid = lane & 3;
    const float* Bn = g_folded + (size_t)n * 256 * PACT;

    float acc[2][8][4] = {};

    auto stage = [&](int iter) {
        int buf = iter & 1, k0 = iter * 16;
#pragma unroll
        for (int j = 0; j < 8; j++) {
            int e = tid + j * 256;
            int col = e & 127, kk = e >> 7;
            int p = p0 + col;
            float v = (p < PACT) ? Bn[(size_t)(k0 + kk) * PACT + p] : 0.f;
            Bs[buf][kk >> 3][col >> 3][(col & 7) * 8 + (kk & 3) * 2 + ((kk >> 2) & 1)] = f2tf(v);
        }
    };
    stage(0);
    __syncthreads();

    const int mtg0 = (o0 >> 4) + warp_m * 2;
    for (int iter = 0; iter < 16; iter++) {
        if (iter + 1 < 16) stage(iter + 1);
        int buf = iter & 1;
#pragma unroll
        for (int ks = 0; ks < 2; ks++) {
            int ksg = iter * 2 + ks;
            unsigned a[2][4];
#pragma unroll
            for (int mt = 0; mt < 2; mt++) {
                uint4 av = ((const uint4*)g_wfrag2)[((mtg0 + mt) * 32 + ksg) * 32 + lane];
                a[mt][0] = av.x; a[mt][1] = av.y; a[mt][2] = av.z; a[mt][3] = av.w;
            }
#pragma unroll
            for (int nt = 0; nt < 8; nt++) {
                const unsigned* bp = &Bs[buf][ks][warp_n * 8 + nt][lane * 2];
                unsigned b0 = bp[0], b1 = bp[1];
                mma_tf32(acc[0][nt], a[0], b0, b1);
                mma_tf32(acc[1][nt], a[1], b0, b1);
            }
        }
        __syncthreads();
    }

    float* outb = g_pout + (size_t)n * 256 * PACT;
#pragma unroll
    for (int mt = 0; mt < 2; mt++) {
        int row0 = o0 + warp_m * 32 + mt * 16 + gid;
#pragma unroll
        for (int half = 0; half < 2; half++) {
            int o = row0 + half * 8;
            float bv = b_proj[o];
#pragma unroll
            for (int nt = 0; nt < 8; nt++) {
                int col = p0 + warp_n * 64 + nt * 8 + ctid * 2;
                if (col < PACT)     outb[(size_t)o * PACT + col]     = acc[mt][nt][half * 2 + 0] + bv;
                if (col + 1 < PACT) outb[(size_t)o * PACT + col + 1] = acc[mt][nt][half * 2 + 1] + bv;
            }
        }
    }
}

// ---------------------------------------------------------------------------
// Attention: one block per (n, h, s). hd=64, L=16.
// ---------------------------------------------------------------------------
__global__ __launch_bounds__(256) void attn_kernel() {
    const int s = blockIdx.x;          // 0..99
    const int h = blockIdx.y;          // 0..3
    const int n = blockIdx.z;          // 0..31
    const int i  = s / 10;
    const int i2 = s - i * 10;

    __shared__ float qs[64][16];
    __shared__ float ks[64][16];
    __shared__ float vs[64][16];
    __shared__ float sc[16][17];

    const int tid = threadIdx.x;
    const float* base = g_qkva + (size_t)n * 768 * PACT + (size_t)h * 64 * PACT;

    for (int t = tid; t < 1024; t += 256) {
        int d = t >> 4, l = t & 15;
        int j = l >> 2, j2 = l & 3;
        int p = (2 * i + j) * 22 + (2 * i2 + j2);
        size_t off = (size_t)d * PACT + p;
        qs[d][l] = base[off];
        ks[d][l] = base[off + (size_t)256 * PACT];
        vs[d][l] = base[off + (size_t)512 * PACT];
    }
    __syncthreads();

    const int x = tid >> 4, y = tid & 15;
    float sacc = 0.f;
#pragma unroll 16
    for (int d = 0; d < 64; d++) sacc += qs[d][x] * ks[d][y];
    sacc *= 0.125f;
    sc[x][y] = sacc;
    __syncthreads();

    float mx = -1e30f;
#pragma unroll
    for (int yy = 0; yy < 16; yy++) mx = fmaxf(mx, sc[x][yy]);
    float e = __expf(sacc - mx);
    __syncthreads();
    sc[x][y] = e;
    __syncthreads();
    float sum = 0.f;
#pragma unroll
    for (int yy = 0; yy < 16; yy++) sum += sc[x][yy];
    float attn = e / sum;
    __syncthreads();
    sc[x][y] = attn;
    __syncthreads();

    const int dg = tid >> 4;
    const int xx = tid & 15;
    float* ob = g_oscr + ((size_t)(n * 4 + h) * 64) * 1600 + (size_t)s * 16;
#pragma unroll
    for (int dd = 0; dd < 4; dd++) {
        int d = dg * 4 + dd;
        float o = 0.f;
#pragma unroll
        for (int yy = 0; yy < 16; yy++) o += sc[xx][yy] * vs[d][yy];
        ob[(size_t)d * 1600 + xx] = o;
    }
}

// ---------------------------------------------------------------------------
// Fold (gather, deterministic)
// ---------------------------------------------------------------------------
__global__ __launch_bounds__(256) void fold_kernel() {
    int idx = blockIdx.x * 256 + threadIdx.x;
    const int total = NB * 256 * PACT;
    if (idx >= total) return;
    int p  = idx % PACT;
    int nc = idx / PACT;
    int c = nc & 255;
    int n = nc >> 8;
    int m  = p / 22;
    int m2 = p - m * 22;
    int h = c >> 6, d = c & 63;
    const float* ob = g_oscr + (size_t)((n * 4 + h) * 64 + d) * 1600;
    float acc = 0.f;
    for (int ja = (m & 1); ja < 4; ja += 2) {
        int ia2 = m - ja;
        if (ia2 < 0 || ia2 > 18) continue;
        int ia = ia2 >> 1;
        for (int jb = (m2 & 1); jb < 4; jb += 2) {
            int ib2 = m2 - jb;
            if (ib2 < 0 || ib2 > 18) continue;
            int ib = ib2 >> 1;
            acc += ob[(ia * 10 + ib) * 16 + ja * 4 + jb];
        }
    }
    g_folded[idx] = acc;
}

// ---------------------------------------------------------------------------
// Writeout: full output = bias everywhere, gathered proj value at active px
// ---------------------------------------------------------------------------
__global__ __launch_bounds__(256) void writeout(float* __restrict__ out,
                                                const float* __restrict__ b_proj) {
    size_t i4 = (size_t)blockIdx.x * 256 + threadIdx.x;
    if (i4 >= 8388608u) return;
    int ww0 = (int)(i4 & 15) * 4;
    int hh  = (int)(i4 >> 4) & 63;
    int c   = (int)(i4 >> 10) & 255;
    int n   = (int)(i4 >> 18);
    float bv = b_proj[c];
    float4 r = make_float4(bv, bv, bv, bv);
    if (hh % 3 == 0) {
        const float* pr = g_pout + ((size_t)(n * 256 + c)) * PACT + (hh / 3) * 22;
        if ((ww0 + 0) % 3 == 0) r.x = pr[(ww0 + 0) / 3];
        if ((ww0 + 1) % 3 == 0) r.y = pr[(ww0 + 1) / 3];
        if ((ww0 + 2) % 3 == 0) r.z = pr[(ww0 + 2) / 3];
        if ((ww0 + 3) % 3 == 0) r.w = pr[(ww0 + 3) / 3];
    }
    ((float4*)out)[i4] = r;
}

extern "C" void kernel_launch(void* const* d_in, const int* in_sizes, int n_in,
                              void* d_out, int out_size) {
    const float* q      = (const float*)d_in[0];
    const float* w_q    = (const float*)d_in[1];
    const float* b_q    = (const float*)d_in[2];
    const float* w_kv   = (const float*)d_in[3];
    const float* b_kv   = (const float*)d_in[4];
    const float* w_proj = (const float*)d_in[5];
    const float* b_proj = (const float*)d_in[6];
    float* out = (float*)d_out;

    prep_kernel<<<260, 256>>>(w_q, b_q, w_kv, b_kv, w_proj);
    gemm_qkv_tc<<<dim3(4, 6, NB), 256>>>(q);
    attn_kernel<<<dim3(100, 4, NB), 256>>>();
    fold_kernel<<<dim3((NB * 256 * PACT + 255) / 256), 256>>>();
    gemm_proj_tc<<<dim3(4, 2, NB), 256>>>(b_proj);
    writeout<<<32768, 256>>>(out, b_proj);
}

// round 3
// speedup vs baseline: 1.6924x; 1.1103x over previous
#include <cuda_runtime.h>
#include <cstdint>

#define PACT 484      // 22*22 active pixels
#define NB   32

// Scratch (static device allocations - allowed)
__device__ float    g_qkva [(size_t)NB * 768 * PACT];    // qp | k | v at active pixels
__device__ float    g_oscr [(size_t)NB * 4 * 64 * 1600]; // o patches [n][h][d][s(100)*16+l]
__device__ float    g_folded[(size_t)NB * 256 * PACT];   // folded at active pixels
__device__ float    g_pout [(size_t)NB * 256 * PACT];    // proj output at active pixels
__device__ unsigned g_wfrag1[48 * 32 * 128];             // [w_q;w_kv] tf32 A-fragments
__device__ unsigned g_wfrag2[16 * 32 * 128];             // w_proj tf32 A-fragments
__device__ unsigned g_qpack[(size_t)NB * 32 * 512 * 8];  // gathered q, tf32 B-fragment layout
__device__ float    g_bias768[768];

__device__ __forceinline__ unsigned f2tf(float f) {
    unsigned r; asm("cvt.rna.tf32.f32 %0, %1;" : "=r"(r) : "f"(f)); return r;
}

__device__ __forceinline__ void mma_tf32(float* d, const unsigned* a, unsigned b0, unsigned b1) {
    asm("mma.sync.aligned.m16n8k8.row.col.f32.tf32.tf32.f32 "
        "{%0,%1,%2,%3},{%4,%5,%6,%7},{%8,%9},{%0,%1,%2,%3};\n"
        : "+f"(d[0]), "+f"(d[1]), "+f"(d[2]), "+f"(d[3])
        : "r"(a[0]), "r"(a[1]), "r"(a[2]), "r"(a[3]), "r"(b0), "r"(b1));
}

// ---------------------------------------------------------------------------
// Prep: weights -> mma A-fragment-native tf32 layout, concat biases.
// ---------------------------------------------------------------------------
__global__ __launch_bounds__(256) void prep_kernel(const float* __restrict__ w_q,
                                                   const float* __restrict__ b_q,
                                                   const float* __restrict__ w_kv,
                                                   const float* __restrict__ b_kv,
                                                   const float* __restrict__ w_proj) {
    int t = blockIdx.x * 256 + threadIdx.x;
    if (t < 49152) {                      // 48 mt * 32 ks * 32 lanes
        int lane = t & 31, ks = (t >> 5) & 31, mtg = t >> 10;
        int gid = lane >> 2, ctid = lane & 3;
        int r0 = mtg * 16 + gid, r1 = r0 + 8;
        int k0 = ks * 8 + ctid, k1 = k0 + 4;
        const float* W; int rb;
        if (r0 < 256) { W = w_q; rb = 0; } else { W = w_kv; rb = 256; }
        uint4 v = make_uint4(f2tf(W[(size_t)(r0 - rb) * 256 + k0]),
                             f2tf(W[(size_t)(r1 - rb) * 256 + k0]),
                             f2tf(W[(size_t)(r0 - rb) * 256 + k1]),
                             f2tf(W[(size_t)(r1 - rb) * 256 + k1]));
        ((uint4*)g_wfrag1)[t] = v;
    } else if (t < 49152 + 16384) {       // 16 mt * 32 ks * 32 lanes
        int u = t - 49152;
        int lane = u & 31, ks = (u >> 5) & 31, mtg = u >> 10;
        int gid = lane >> 2, ctid = lane & 3;
        int r0 = mtg * 16 + gid, r1 = r0 + 8;
        int k0 = ks * 8 + ctid, k1 = k0 + 4;
        uint4 v = make_uint4(f2tf(w_proj[(size_t)r0 * 256 + k0]),
                             f2tf(w_proj[(size_t)r1 * 256 + k0]),
                             f2tf(w_proj[(size_t)r0 * 256 + k1]),
                             f2tf(w_proj[(size_t)r1 * 256 + k1]));
        ((uint4*)g_wfrag2)[u] = v;
    } else if (t < 49152 + 16384 + 768) {
        int o = t - 49152 - 16384;
        g_bias768[o] = (o < 256) ? b_q[o] : b_kv[o - 256];
    }
}

// ---------------------------------------------------------------------------
// Pack: gather q at active pixels -> tf32 B-fragment-native layout.
// g_qpack[((n*32+kg)*512 + p)*8 + idx], idx = (kk&3)*2 + (kk>>2), kk = k&7
// ---------------------------------------------------------------------------
__global__ __launch_bounds__(256) void pack_q(const float* __restrict__ q) {
    const int p  = blockIdx.x * 256 + threadIdx.x;   // 0..511
    const int kg = blockIdx.y;                       // 0..31
    const int n  = blockIdx.z;
    const float* qn = q + (size_t)n * 256 * 4096;
    unsigned o[8];
    if (p < PACT) {
        int m = p / 22, m2 = p - m * 22;
        size_t base = (size_t)(kg * 8) * 4096 + m * 192 + m2 * 3;
#pragma unroll
        for (int kk = 0; kk < 8; kk++)
            o[(kk & 3) * 2 + (kk >> 2)] = f2tf(qn[base + (size_t)kk * 4096]);
    } else {
#pragma unroll
        for (int i = 0; i < 8; i++) o[i] = 0u;
    }
    uint4* dst = (uint4*)(g_qpack + ((size_t)(n * 32 + kg) * 512 + p) * 8);
    dst[0] = make_uint4(o[0], o[1], o[2], o[3]);
    dst[1] = make_uint4(o[4], o[5], o[6], o[7]);
}

// ---------------------------------------------------------------------------
// TF32 GEMM1: per n, OUT(768,484) = [w_q;w_kv] @ gather(q) + bias
// B staged by straight memcpy from g_qpack; A fragments register-prefetched.
// ---------------------------------------------------------------------------
__global__ __launch_bounds__(256, 2) void gemm_qkv_tc() {
    __shared__ unsigned Bs[2][2][1024];   // 16 KB, flat idx = p_local*8 + idx
    const int n = blockIdx.z, o0 = blockIdx.y * 128, p0 = blockIdx.x * 128;
    const int tid = threadIdx.x, lane = tid & 31, wid = tid >> 5;
    const int warp_m = wid >> 1, warp_n = wid & 1;
    const int gid = lane >> 2, ctid = lane & 3;

    float acc[2][8][4] = {};

    const uint4* src = (const uint4*)(g_qpack + ((size_t)(n * 32) * 512 + p0) * 8);
    // per kg chunk: 512 p-slots * 8 -> tile of 128 p = 256 uint4 starting at p0*2 (uint4 units)
    auto stage = [&](int iter) {
        int buf = iter & 1;
#pragma unroll
        for (int ks = 0; ks < 2; ks++) {
            int kg = iter * 2 + ks;
            ((uint4*)Bs[buf][ks])[tid] = src[(size_t)kg * 1024 + tid];
        }
    };
    stage(0);
    __syncthreads();

    const int mtg0 = (o0 >> 4) + warp_m * 2;
    uint4 a_next[2];
#pragma unroll
    for (int mt = 0; mt < 2; mt++)
        a_next[mt] = ((const uint4*)g_wfrag1)[((mtg0 + mt) * 32 + 0) * 32 + lane];

    for (int iter = 0; iter < 16; iter++) {
        if (iter + 1 < 16) stage(iter + 1);
        int buf = iter & 1;
#pragma unroll
        for (int ks = 0; ks < 2; ks++) {
            int ksg = iter * 2 + ks;
            uint4 a_cur[2]; a_cur[0] = a_next[0]; a_cur[1] = a_next[1];
            if (ksg + 1 < 32) {
#pragma unroll
                for (int mt = 0; mt < 2; mt++)
                    a_next[mt] = ((const uint4*)g_wfrag1)[((mtg0 + mt) * 32 + ksg + 1) * 32 + lane];
            }
            unsigned a0[4] = {a_cur[0].x, a_cur[0].y, a_cur[0].z, a_cur[0].w};
            unsigned a1[4] = {a_cur[1].x, a_cur[1].y, a_cur[1].z, a_cur[1].w};
#pragma unroll
            for (int nt = 0; nt < 8; nt++) {
                const unsigned* bp = &Bs[buf][ks][warp_n * 512 + nt * 64 + lane * 2];
                unsigned b0 = bp[0], b1 = bp[1];
                mma_tf32(acc[0][nt], a0, b0, b1);
                mma_tf32(acc[1][nt], a1, b0, b1);
            }
        }
        __syncthreads();
    }

    float* outb = g_qkva + (size_t)n * 768 * PACT;
#pragma unroll
    for (int mt = 0; mt < 2; mt++) {
        int row0 = o0 + warp_m * 32 + mt * 16 + gid;
#pragma unroll
        for (int half = 0; half < 2; half++) {
            int o = row0 + half * 8;
            float bv = g_bias768[o];
#pragma unroll
            for (int nt = 0; nt < 8; nt++) {
                int col = p0 + warp_n * 64 + nt * 8 + ctid * 2;
                if (col < PACT)     outb[(size_t)o * PACT + col]     = acc[mt][nt][half * 2 + 0] + bv;
                if (col + 1 < PACT) outb[(size_t)o * PACT + col + 1] = acc[mt][nt][half * 2 + 1] + bv;
            }
        }
    }
}

// ---------------------------------------------------------------------------
// TF32 GEMM2: per n, POUT(256,484) = w_proj @ folded + b_proj
// B staged coalesced from g_folded (reg-permute to fragment layout);
// A fragments register-prefetched.
// ---------------------------------------------------------------------------
__global__ __launch_bounds__(256, 2) void gemm_proj_tc(const float* __restrict__ b_proj) {
    __shared__ unsigned Bs[2][2][1024];
    const int n = blockIdx.z, o0 = blockIdx.y * 128, p0 = blockIdx.x * 128;
    const int tid = threadIdx.x, lane = tid & 31, wid = tid >> 5;
    const int warp_m = wid >> 1, warp_n = wid & 1;
    const int gid = lane >> 2, ctid = lane & 3;
    const float* Bn = g_folded + (size_t)n * 256 * PACT;

    float acc[2][8][4] = {};

    const int pl = tid & 127, kh = tid >> 7;
    const int pg = p0 + pl;
    auto stage = [&](int iter) {
        int buf = iter & 1, k0 = iter * 16 + kh * 8;
        unsigned o[8];
#pragma unroll
        for (int kk = 0; kk < 8; kk++) {
            float v = (pg < PACT) ? Bn[(size_t)(k0 + kk) * PACT + pg] : 0.f;
            o[(kk & 3) * 2 + (kk >> 2)] = f2tf(v);
        }
        uint4* dst = (uint4*)&Bs[buf][kh][pl * 8];
        dst[0] = make_uint4(o[0], o[1], o[2], o[3]);
        dst[1] = make_uint4(o[4], o[5], o[6], o[7]);
    };
    stage(0);
    __syncthreads();

    const int mtg0 = (o0 >> 4) + warp_m * 2;
    uint4 a_next[2];
#pragma unroll
    for (int mt = 0; mt < 2; mt++)
        a_next[mt] = ((const uint4*)g_wfrag2)[((mtg0 + mt) * 32 + 0) * 32 + lane];

    for (int iter = 0; iter < 16; iter++) {
        if (iter + 1 < 16) stage(iter + 1);
        int buf = iter & 1;
#pragma unroll
        for (int ks = 0; ks < 2; ks++) {
            int ksg = iter * 2 + ks;
            uint4 a_cur[2]; a_cur[0] = a_next[0]; a_cur[1] = a_next[1];
            if (ksg + 1 < 32) {
#pragma unroll
                for (int mt = 0; mt < 2; mt++)
                    a_next[mt] = ((const uint4*)g_wfrag2)[((mtg0 + mt) * 32 + ksg + 1) * 32 + lane];
            }
            unsigned a0[4] = {a_cur[0].x, a_cur[0].y, a_cur[0].z, a_cur[0].w};
            unsigned a1[4] = {a_cur[1].x, a_cur[1].y, a_cur[1].z, a_cur[1].w};
#pragma unroll
            for (int nt = 0; nt < 8; nt++) {
                const unsigned* bp = &Bs[buf][ks][warp_n * 512 + nt * 64 + lane * 2];
                unsigned b0 = bp[0], b1 = bp[1];
                mma_tf32(acc[0][nt], a0, b0, b1);
                mma_tf32(acc[1][nt], a1, b0, b1);
            }
        }
        __syncthreads();
    }

    float* outb = g_pout + (size_t)n * 256 * PACT;
#pragma unroll
    for (int mt = 0; mt < 2; mt++) {
        int row0 = o0 + warp_m * 32 + mt * 16 + gid;
#pragma unroll
        for (int half = 0; half < 2; half++) {
            int o = row0 + half * 8;
            float bv = b_proj[o];
#pragma unroll
            for (int nt = 0; nt < 8; nt++) {
                int col = p0 + warp_n * 64 + nt * 8 + ctid * 2;
                if (col < PACT)     outb[(size_t)o * PACT + col]     = acc[mt][nt][half * 2 + 0] + bv;
                if (col + 1 < PACT) outb[(size_t)o * PACT + col + 1] = acc[mt][nt][half * 2 + 1] + bv;
            }
        }
    }
}

// ---------------------------------------------------------------------------
// Attention: one block per (n, h, s). hd=64, L=16.
// Tiles stored [l][d] (stride 68) -> float4 dot products; shfl softmax; 2 syncs.
// ---------------------------------------------------------------------------
__global__ __launch_bounds__(256) void attn_kernel() {
    const int s = blockIdx.x;          // 0..99
    const int h = blockIdx.y;          // 0..3
    const int n = blockIdx.z;          // 0..31
    const int i  = s / 10;
    const int i2 = s - i * 10;

    __shared__ float qs2[16][68];
    __shared__ float ks2[16][68];
    __shared__ float vs2[16][68];
    __shared__ float sc[16][17];

    const int tid = threadIdx.x;
    const float* base = g_qkva + (size_t)n * 768 * PACT + (size_t)h * 64 * PACT;

    // Staging: float2 granules. e in [0,512): d=e>>3, j=(e&7)>>1, j2h=e&1
#pragma unroll
    for (int r = 0; r < 2; r++) {
        int e = tid + r * 256;
        int d = e >> 3, rem = e & 7;
        int j = rem >> 1, j2h = rem & 1;
        int p = (2 * i + j) * 22 + 2 * i2 + j2h * 2;
        int l = j * 4 + j2h * 2;
        size_t off = (size_t)d * PACT + p;
        float2 qv = *(const float2*)&base[off];
        float2 kv = *(const float2*)&base[off + (size_t)256 * PACT];
        float2 vv = *(const float2*)&base[off + (size_t)512 * PACT];
        qs2[l][d] = qv.x; qs2[l + 1][d] = qv.y;
        ks2[l][d] = kv.x; ks2[l + 1][d] = kv.y;
        vs2[l][d] = vv.x; vs2[l + 1][d] = vv.y;
    }
    __syncthreads();

    const int x = tid >> 4, y = tid & 15;
    float sacc = 0.f;
#pragma unroll
    for (int dc = 0; dc < 16; dc++) {
        float4 qv = *(const float4*)&qs2[x][dc * 4];
        float4 kv = *(const float4*)&ks2[y][dc * 4];
        sacc += qv.x * kv.x + qv.y * kv.y + qv.z * kv.z + qv.w * kv.w;
    }
    sacc *= 0.125f;

    // softmax across y (16 lanes of the half-warp)
    float mx = sacc;
#pragma unroll
    for (int off = 8; off >= 1; off >>= 1)
        mx = fmaxf(mx, __shfl_xor_sync(0xffffffffu, mx, off));
    float e = __expf(sacc - mx);
    float sum = e;
#pragma unroll
    for (int off = 8; off >= 1; off >>= 1)
        sum += __shfl_xor_sync(0xffffffffu, sum, off);
    sc[x][y] = e / sum;
    __syncthreads();

    // o[d][x] = sum_y attn[x][y] * v[d][y]
    const int dg = tid >> 4;   // 0..15 -> d = dg*4..dg*4+3
    const int xx = tid & 15;
    float4 o = make_float4(0.f, 0.f, 0.f, 0.f);
#pragma unroll
    for (int yy = 0; yy < 16; yy++) {
        float a = sc[xx][yy];
        float4 vv = *(const float4*)&vs2[yy][dg * 4];
        o.x += a * vv.x; o.y += a * vv.y; o.z += a * vv.z; o.w += a * vv.w;
    }
    float* ob = g_oscr + ((size_t)(n * 4 + h) * 64) * 1600 + (size_t)s * 16 + xx;
    ob[(size_t)(dg * 4 + 0) * 1600] = o.x;
    ob[(size_t)(dg * 4 + 1) * 1600] = o.y;
    ob[(size_t)(dg * 4 + 2) * 1600] = o.z;
    ob[(size_t)(dg * 4 + 3) * 1600] = o.w;
}

// ---------------------------------------------------------------------------
// Fold via shared memory: one block per (n, c). Coalesced in, coalesced out.
// ---------------------------------------------------------------------------
__global__ __launch_bounds__(256) void fold_kernel() {
    __shared__ float sob[1600];
    const int nc = blockIdx.x;          // n*256 + c
    const float* ob = g_oscr + (size_t)nc * 1600;   // layout matches [n][h][d]
    const int tid = threadIdx.x;
#pragma unroll
    for (int t = tid; t < 400; t += 256)
        ((float4*)sob)[t] = ((const float4*)ob)[t];
    __syncthreads();

    float* dst = g_folded + (size_t)nc * PACT;
    for (int p = tid; p < PACT; p += 256) {
        int m  = p / 22;
        int m2 = p - m * 22;
        float acc = 0.f;
#pragma unroll
        for (int ja = 0; ja < 4; ja++) {
            int ia2 = m - ja;
            if ((ia2 & 1) || ia2 < 0 || ia2 > 18) continue;
            int ia = ia2 >> 1;
#pragma unroll
            for (int jb = 0; jb < 4; jb++) {
                int ib2 = m2 - jb;
                if ((ib2 & 1) || ib2 < 0 || ib2 > 18) continue;
                int ib = ib2 >> 1;
                acc += sob[(ia * 10 + ib) * 16 + ja * 4 + jb];
            }
        }
        dst[p] = acc;
    }
}

// ---------------------------------------------------------------------------
// Writeout: full output = bias everywhere, gathered proj value at active px
// ---------------------------------------------------------------------------
__global__ __launch_bounds__(256) void writeout(float* __restrict__ out,
                                                const float* __restrict__ b_proj) {
    size_t i4 = (size_t)blockIdx.x * 256 + threadIdx.x;
    if (i4 >= 8388608u) return;
    int ww0 = (int)(i4 & 15) * 4;
    int hh  = (int)(i4 >> 4) & 63;
    int c   = (int)(i4 >> 10) & 255;
    int n   = (int)(i4 >> 18);
    float bv = b_proj[c];
    float4 r = make_float4(bv, bv, bv, bv);
    if (hh % 3 == 0) {
        const float* pr = g_pout + ((size_t)(n * 256 + c)) * PACT + (hh / 3) * 22;
        if ((ww0 + 0) % 3 == 0) r.x = pr[(ww0 + 0) / 3];
        if ((ww0 + 1) % 3 == 0) r.y = pr[(ww0 + 1) / 3];
        if ((ww0 + 2) % 3 == 0) r.z = pr[(ww0 + 2) / 3];
        if ((ww0 + 3) % 3 == 0) r.w = pr[(ww0 + 3) / 3];
    }
    ((float4*)out)[i4] = r;
}

extern "C" void kernel_launch(void* const* d_in, const int* in_sizes, int n_in,
                              void* d_out, int out_size) {
    const float* q      = (const float*)d_in[0];
    const float* w_q    = (const float*)d_in[1];
    const float* b_q    = (const float*)d_in[2];
    const float* w_kv   = (const float*)d_in[3];
    const float* b_kv   = (const float*)d_in[4];
    const float* w_proj = (const float*)d_in[5];
    const float* b_proj = (const float*)d_in[6];
    float* out = (float*)d_out;

    prep_kernel<<<260, 256>>>(w_q, b_q, w_kv, b_kv, w_proj);
    pack_q<<<dim3(2, 32, NB), 256>>>(q);
    gemm_qkv_tc<<<dim3(4, 6, NB), 256>>>();
    attn_kernel<<<dim3(100, 4, NB), 256>>>();
    fold_kernel<<<dim3(NB * 256), 256>>>();
    gemm_proj_tc<<<dim3(4, 2, NB), 256>>>(b_proj);
    writeout<<<32768, 256>>>(out, b_proj);
}

// round 5
// speedup vs baseline: 1.7340x; 1.0246x over previous
#include <cuda_runtime.h>
#include <cstdint>

#define PACT 484      // 22*22 active pixels
#define NB   32

// Scratch (static device allocations - allowed)
__device__ float    g_qkva [(size_t)NB * 768 * PACT];    // qp | k | v at active pixels
__device__ float    g_oscr [(size_t)NB * 4 * 100 * 1024];// o patches [n][h][s][l(16)][d(64)]
__device__ float    g_folded[(size_t)NB * 256 * PACT];   // folded at active pixels
__device__ float    g_pout [(size_t)NB * 256 * PACT];    // proj output at active pixels
__device__ unsigned g_wfrag1[48 * 32 * 128];             // [w_q;w_kv] tf32 A-fragments
__device__ unsigned g_wfrag2[16 * 32 * 128];             // w_proj tf32 A-fragments
__device__ unsigned g_qpack[(size_t)NB * 32 * 512 * 8];  // gathered q, tf32 B-fragment layout
__device__ float    g_bias768[768];

__device__ __forceinline__ unsigned f2tf(float f) {
    unsigned r; asm("cvt.rna.tf32.f32 %0, %1;" : "=r"(r) : "f"(f)); return r;
}

__device__ __forceinline__ void mma_tf32(float* d, const unsigned* a, unsigned b0, unsigned b1) {
    asm("mma.sync.aligned.m16n8k8.row.col.f32.tf32.tf32.f32 "
        "{%0,%1,%2,%3},{%4,%5,%6,%7},{%8,%9},{%0,%1,%2,%3};\n"
        : "+f"(d[0]), "+f"(d[1]), "+f"(d[2]), "+f"(d[3])
        : "r"(a[0]), "r"(a[1]), "r"(a[2]), "r"(a[3]), "r"(b0), "r"(b1));
}

// ---------------------------------------------------------------------------
// Prep: weights -> mma A-fragment-native tf32 layout, concat biases.
// ---------------------------------------------------------------------------
__global__ __launch_bounds__(256) void prep_kernel(const float* __restrict__ w_q,
                                                   const float* __restrict__ b_q,
                                                   const float* __restrict__ w_kv,
                                                   const float* __restrict__ b_kv,
                                                   const float* __restrict__ w_proj) {
    int t = blockIdx.x * 256 + threadIdx.x;
    if (t < 49152) {                      // 48 mt * 32 ks * 32 lanes
        int lane = t & 31, ks = (t >> 5) & 31, mtg = t >> 10;
        int gid = lane >> 2, ctid = lane & 3;
        int r0 = mtg * 16 + gid, r1 = r0 + 8;
        int k0 = ks * 8 + ctid, k1 = k0 + 4;
        const float* W; int rb;
        if (r0 < 256) { W = w_q; rb = 0; } else { W = w_kv; rb = 256; }
        uint4 v = make_uint4(f2tf(W[(size_t)(r0 - rb) * 256 + k0]),
                             f2tf(W[(size_t)(r1 - rb) * 256 + k0]),
                             f2tf(W[(size_t)(r0 - rb) * 256 + k1]),
                             f2tf(W[(size_t)(r1 - rb) * 256 + k1]));
        ((uint4*)g_wfrag1)[t] = v;
    } else if (t < 49152 + 16384) {       // 16 mt * 32 ks * 32 lanes
        int u = t - 49152;
        int lane = u & 31, ks = (u >> 5) & 31, mtg = u >> 10;
        int gid = lane >> 2, ctid = lane & 3;
        int r0 = mtg * 16 + gid, r1 = r0 + 8;
        int k0 = ks * 8 + ctid, k1 = k0 + 4;
        uint4 v = make_uint4(f2tf(w_proj[(size_t)r0 * 256 + k0]),
                             f2tf(w_proj[(size_t)r1 * 256 + k0]),
                             f2tf(w_proj[(size_t)r0 * 256 + k1]),
                             f2tf(w_proj[(size_t)r1 * 256 + k1]));
        ((uint4*)g_wfrag2)[u] = v;
    } else if (t < 49152 + 16384 + 768) {
        int o = t - 49152 - 16384;
        g_bias768[o] = (o < 256) ? b_q[o] : b_kv[o - 256];
    }
}

// ---------------------------------------------------------------------------
// Pack: gather q at active pixels -> tf32 B-fragment-native layout.
// ---------------------------------------------------------------------------
__global__ __launch_bounds__(256) void pack_q(const float* __restrict__ q) {
    const int p  = blockIdx.x * 256 + threadIdx.x;   // 0..511
    const int kg = blockIdx.y;                       // 0..31
    const int n  = blockIdx.z;
    const float* qn = q + (size_t)n * 256 * 4096;
    unsigned o[8];
    if (p < PACT) {
        int m = p / 22, m2 = p - m * 22;
        size_t base = (size_t)(kg * 8) * 4096 + m * 192 + m2 * 3;
#pragma unroll
        for (int kk = 0; kk < 8; kk++)
            o[(kk & 3) * 2 + (kk >> 2)] = f2tf(qn[base + (size_t)kk * 4096]);
    } else {
#pragma unroll
        for (int i = 0; i < 8; i++) o[i] = 0u;
    }
    uint4* dst = (uint4*)(g_qpack + ((size_t)(n * 32 + kg) * 512 + p) * 8);
    dst[0] = make_uint4(o[0], o[1], o[2], o[3]);
    dst[1] = make_uint4(o[4], o[5], o[6], o[7]);
}

// ---------------------------------------------------------------------------
// TF32 GEMM1: per n, OUT(768,484) = [w_q;w_kv] @ gather(q) + bias
// ---------------------------------------------------------------------------
__global__ __launch_bounds__(256, 2) void gemm_qkv_tc() {
    __shared__ unsigned Bs[2][2][1024];   // 16 KB
    const int n = blockIdx.z, o0 = blockIdx.y * 128, p0 = blockIdx.x * 128;
    const int tid = threadIdx.x, lane = tid & 31, wid = tid >> 5;
    const int warp_m = wid >> 1, warp_n = wid & 1;
    const int gid = lane >> 2, ctid = lane & 3;

    float acc[2][8][4] = {};

    const uint4* src = (const uint4*)(g_qpack + ((size_t)(n * 32) * 512 + p0) * 8);
    auto stage = [&](int iter) {
        int buf = iter & 1;
#pragma unroll
        for (int ks = 0; ks < 2; ks++) {
            int kg = iter * 2 + ks;
            ((uint4*)Bs[buf][ks])[tid] = src[(size_t)kg * 1024 + tid];
        }
    };
    stage(0);
    __syncthreads();

    const int mtg0 = (o0 >> 4) + warp_m * 2;
    uint4 a_next[2];
#pragma unroll
    for (int mt = 0; mt < 2; mt++)
        a_next[mt] = ((const uint4*)g_wfrag1)[((mtg0 + mt) * 32 + 0) * 32 + lane];

    for (int iter = 0; iter < 16; iter++) {
        if (iter + 1 < 16) stage(iter + 1);
        int buf = iter & 1;
#pragma unroll
        for (int ks = 0; ks < 2; ks++) {
            int ksg = iter * 2 + ks;
            uint4 a_cur[2]; a_cur[0] = a_next[0]; a_cur[1] = a_next[1];
            if (ksg + 1 < 32) {
#pragma unroll
                for (int mt = 0; mt < 2; mt++)
                    a_next[mt] = ((const uint4*)g_wfrag1)[((mtg0 + mt) * 32 + ksg + 1) * 32 + lane];
            }
            unsigned a0[4] = {a_cur[0].x, a_cur[0].y, a_cur[0].z, a_cur[0].w};
            unsigned a1[4] = {a_cur[1].x, a_cur[1].y, a_cur[1].z, a_cur[1].w};
#pragma unroll
            for (int nt = 0; nt < 8; nt++) {
                const unsigned* bp = &Bs[buf][ks][warp_n * 512 + nt * 64 + lane * 2];
                unsigned b0 = bp[0], b1 = bp[1];
                mma_tf32(acc[0][nt], a0, b0, b1);
                mma_tf32(acc[1][nt], a1, b0, b1);
            }
        }
        __syncthreads();
    }

    float* outb = g_qkva + (size_t)n * 768 * PACT;
#pragma unroll
    for (int mt = 0; mt < 2; mt++) {
        int row0 = o0 + warp_m * 32 + mt * 16 + gid;
#pragma unroll
        for (int half = 0; half < 2; half++) {
            int o = row0 + half * 8;
            float bv = g_bias768[o];
#pragma unroll
            for (int nt = 0; nt < 8; nt++) {
                int col = p0 + warp_n * 64 + nt * 8 + ctid * 2;
                if (col < PACT)     outb[(size_t)o * PACT + col]     = acc[mt][nt][half * 2 + 0] + bv;
                if (col + 1 < PACT) outb[(size_t)o * PACT + col + 1] = acc[mt][nt][half * 2 + 1] + bv;
            }
        }
    }
}

// ---------------------------------------------------------------------------
// TF32 GEMM2: per n, POUT(256,484) = w_proj @ folded + b_proj
// ---------------------------------------------------------------------------
__global__ __launch_bounds__(256, 2) void gemm_proj_tc(const float* __restrict__ b_proj) {
    __shared__ unsigned Bs[2][2][1024];
    const int n = blockIdx.z, o0 = blockIdx.y * 128, p0 = blockIdx.x * 128;
    const int tid = threadIdx.x, lane = tid & 31, wid = tid >> 5;
    const int warp_m = wid >> 1, warp_n = wid & 1;
    const int gid = lane >> 2, ctid = lane & 3;
    const float* Bn = g_folded + (size_t)n * 256 * PACT;

    float acc[2][8][4] = {};

    const int pl = tid & 127, kh = tid >> 7;
    const int pg = p0 + pl;
    auto stage = [&](int iter) {
        int buf = iter & 1, k0 = iter * 16 + kh * 8;
        unsigned o[8];
#pragma unroll
        for (int kk = 0; kk < 8; kk++) {
            float v = (pg < PACT) ? Bn[(size_t)(k0 + kk) * PACT + pg] : 0.f;
            o[(kk & 3) * 2 + (kk >> 2)] = f2tf(v);
        }
        uint4* dst = (uint4*)&Bs[buf][kh][pl * 8];
        dst[0] = make_uint4(o[0], o[1], o[2], o[3]);
        dst[1] = make_uint4(o[4], o[5], o[6], o[7]);
    };
    stage(0);
    __syncthreads();

    const int mtg0 = (o0 >> 4) + warp_m * 2;
    uint4 a_next[2];
#pragma unroll
    for (int mt = 0; mt < 2; mt++)
        a_next[mt] = ((const uint4*)g_wfrag2)[((mtg0 + mt) * 32 + 0) * 32 + lane];

    for (int iter = 0; iter < 16; iter++) {
        if (iter + 1 < 16) stage(iter + 1);
        int buf = iter & 1;
#pragma unroll
        for (int ks = 0; ks < 2; ks++) {
            int ksg = iter * 2 + ks;
            uint4 a_cur[2]; a_cur[0] = a_next[0]; a_cur[1] = a_next[1];
            if (ksg + 1 < 32) {
#pragma unroll
                for (int mt = 0; mt < 2; mt++)
                    a_next[mt] = ((const uint4*)g_wfrag2)[((mtg0 + mt) * 32 + ksg + 1) * 32 + lane];
            }
            unsigned a0[4] = {a_cur[0].x, a_cur[0].y, a_cur[0].z, a_cur[0].w};
            unsigned a1[4] = {a_cur[1].x, a_cur[1].y, a_cur[1].z, a_cur[1].w};
#pragma unroll
            for (int nt = 0; nt < 8; nt++) {
                const unsigned* bp = &Bs[buf][ks][warp_n * 512 + nt * 64 + lane * 2];
                unsigned b0 = bp[0], b1 = bp[1];
                mma_tf32(acc[0][nt], a0, b0, b1);
                mma_tf32(acc[1][nt], a1, b0, b1);
            }
        }
        __syncthreads();
    }

    float* outb = g_pout + (size_t)n * 256 * PACT;
#pragma unroll
    for (int mt = 0; mt < 2; mt++) {
        int row0 = o0 + warp_m * 32 + mt * 16 + gid;
#pragma unroll
        for (int half = 0; half < 2; half++) {
            int o = row0 + half * 8;
            float bv = b_proj[o];
#pragma unroll
            for (int nt = 0; nt < 8; nt++) {
                int col = p0 + warp_n * 64 + nt * 8 + ctid * 2;
                if (col < PACT)     outb[(size_t)o * PACT + col]     = acc[mt][nt][half * 2 + 0] + bv;
                if (col + 1 < PACT) outb[(size_t)o * PACT + col + 1] = acc[mt][nt][half * 2 + 1] + bv;
            }
        }
    }
}

// ---------------------------------------------------------------------------
// Attention (mma): block per (n, h, i-row). 10 warps; warp w = patch s=i*10+w.
// Stage q,k (tf32, q pre-scaled) for 4 image rows = 88 contiguous cols/d-row.
// QK^T: 16 mma. Softmax in registers (quad shfl). AV: 48 mma with 2-term
// tf32 compensation on both attn-probs and V (fp32-accurate output).
// o written [n][h][s][l][d] as float2 from D fragments.
// ---------------------------------------------------------------------------
__global__ __launch_bounds__(320) void attn_kernel() {
    __shared__ unsigned sq[64][88];   // Q(tf32, scaled) -> later V_hi
    __shared__ unsigned sk[64][88];   // K(tf32)         -> later V_lo

    const int i = blockIdx.x;          // patch row 0..9
    const int h = blockIdx.y;
    const int n = blockIdx.z;
    const int tid = threadIdx.x;
    const int lane = tid & 31, wid = tid >> 5;   // wid = i2 = 0..9
    const int gid = lane >> 2, ctid = lane & 3;

    const float* baseq = g_qkva + ((size_t)n * 768 + h * 64) * PACT + i * 44;
    const float* basek = baseq + (size_t)256 * PACT;
    const float* basev = baseq + (size_t)512 * PACT;

    // Stage Q (scaled by hd^-0.5) and K as tf32
    for (int r = wid; r < 64; r += 10) {
        const float* qsrc = baseq + (size_t)r * PACT;
        const float* ksrc = basek + (size_t)r * PACT;
        for (int cc = lane; cc < 88; cc += 32) {
            sq[r][cc] = f2tf(qsrc[cc] * 0.125f);
            sk[r][cc] = f2tf(ksrc[cc]);
        }
    }
    __syncthreads();

    // column map: pixel l -> local col (l>>2)*22 + 2*i2 + (l&3)
    const int cA0 = (gid >> 2) * 22 + (gid & 3) + 2 * wid;   // cmap(gid)
    const int cA1 = cA0 + 44;                                // cmap(gid+8)

    // ---- scores: C[x][y], x rows = l of q, y = l of k ----
    float c0[4] = {}, c1[4] = {};
#pragma unroll
    for (int ks = 0; ks < 8; ks++) {
        int k0 = ks * 8 + ctid;
        unsigned a[4];
        a[0] = sq[k0][cA0]; a[1] = sq[k0][cA1];
        a[2] = sq[k0 + 4][cA0]; a[3] = sq[k0 + 4][cA1];
        unsigned b00 = sk[k0][cA0], b01 = sk[k0 + 4][cA0];
        unsigned b10 = sk[k0][cA1], b11 = sk[k0 + 4][cA1];
        mma_tf32(c0, a, b00, b01);
        mma_tf32(c1, a, b10, b11);
    }

    // ---- softmax over y (rows x=gid and x=gid+8), within each quad ----
    float mx0 = fmaxf(fmaxf(c0[0], c0[1]), fmaxf(c1[0], c1[1]));
    float mx1 = fmaxf(fmaxf(c0[2], c0[3]), fmaxf(c1[2], c1[3]));
#pragma unroll
    for (int off = 1; off <= 2; off <<= 1) {
        mx0 = fmaxf(mx0, __shfl_xor_sync(0xffffffffu, mx0, off));
        mx1 = fmaxf(mx1, __shfl_xor_sync(0xffffffffu, mx1, off));
    }
    float e[2][4];
    e[0][0] = __expf(c0[0] - mx0); e[0][1] = __expf(c0[1] - mx0);
    e[1][0] = __expf(c1[0] - mx0); e[1][1] = __expf(c1[1] - mx0);
    e[0][2] = __expf(c0[2] - mx1); e[0][3] = __expf(c0[3] - mx1);
    e[1][2] = __expf(c1[2] - mx1); e[1][3] = __expf(c1[3] - mx1);
    float s0 = e[0][0] + e[0][1] + e[1][0] + e[1][1];
    float s1 = e[0][2] + e[0][3] + e[1][2] + e[1][3];
#pragma unroll
    for (int off = 1; off <= 2; off <<= 1) {
        s0 += __shfl_xor_sync(0xffffffffu, s0, off);
        s1 += __shfl_xor_sync(0xffffffffu, s1, off);
    }
    float rinv0 = __frcp_rn(s0), rinv1 = __frcp_rn(s1);

    // tf32 split of probs (unnormalized)
    unsigned th[2][4], tl[2][4];
#pragma unroll
    for (int kk = 0; kk < 2; kk++)
#pragma unroll
        for (int r = 0; r < 4; r++) {
            unsigned hi = f2tf(e[kk][r]);
            th[kk][r] = hi;
            tl[kk][r] = f2tf(e[kk][r] - __uint_as_float(hi));
        }

    // ---- restage V (hi into sq, lo into sk) ----
    __syncthreads();
    for (int r = wid; r < 64; r += 10) {
        const float* vsrc = basev + (size_t)r * PACT;
        for (int cc = lane; cc < 88; cc += 32) {
            float v = vsrc[cc];
            unsigned vh = f2tf(v);
            sq[r][cc] = vh;
            sk[r][cc] = f2tf(v - __uint_as_float(vh));
        }
    }
    __syncthreads();

    // ---- AV: D[x][d] = sum_y P[x][y] V[y][d], compensated ----
    float d2[8][4] = {};
    const int srcl0 = gid * 4 + (ctid >> 1);
    const int srcl2 = srcl0 + 2;
    const bool odd = ctid & 1;
#pragma unroll
    for (int kk = 0; kk < 2; kk++) {
        unsigned ah[4], al[4];
        {
            unsigned v0 = __shfl_sync(0xffffffffu, th[kk][0], srcl0);
            unsigned v1 = __shfl_sync(0xffffffffu, th[kk][1], srcl0);
            ah[0] = odd ? v1 : v0;
            v0 = __shfl_sync(0xffffffffu, th[kk][2], srcl0);
            v1 = __shfl_sync(0xffffffffu, th[kk][3], srcl0);
            ah[1] = odd ? v1 : v0;
            v0 = __shfl_sync(0xffffffffu, th[kk][0], srcl2);
            v1 = __shfl_sync(0xffffffffu, th[kk][1], srcl2);
            ah[2] = odd ? v1 : v0;
            v0 = __shfl_sync(0xffffffffu, th[kk][2], srcl2);
            v1 = __shfl_sync(0xffffffffu, th[kk][3], srcl2);
            ah[3] = odd ? v1 : v0;
            v0 = __shfl_sync(0xffffffffu, tl[kk][0], srcl0);
            v1 = __shfl_sync(0xffffffffu, tl[kk][1], srcl0);
            al[0] = odd ? v1 : v0;
            v0 = __shfl_sync(0xffffffffu, tl[kk][2], srcl0);
            v1 = __shfl_sync(0xffffffffu, tl[kk][3], srcl0);
            al[1] = odd ? v1 : v0;
            v0 = __shfl_sync(0xffffffffu, tl[kk][0], srcl2);
            v1 = __shfl_sync(0xffffffffu, tl[kk][1], srcl2);
            al[2] = odd ? v1 : v0;
            v0 = __shfl_sync(0xffffffffu, tl[kk][2], srcl2);
            v1 = __shfl_sync(0xffffffffu, tl[kk][3], srcl2);
            al[3] = odd ? v1 : v0;
        }
        int cv0 = kk * 44 + 2 * wid + ctid;   // cmap(kk*8+ctid)
        int cv1 = cv0 + 22;                   // cmap(kk*8+ctid+4)
#pragma unroll
        for (int nt = 0; nt < 8; nt++) {
            int vr = nt * 8 + gid;
            unsigned b0h = sq[vr][cv0], b1h = sq[vr][cv1];
            unsigned b0l = sk[vr][cv0], b1l = sk[vr][cv1];
            mma_tf32(d2[nt], ah, b0h, b1h);
            mma_tf32(d2[nt], al, b0h, b1h);
            mma_tf32(d2[nt], ah, b0l, b1l);
        }
    }

    // ---- write o[s][l][d], normalized ----
    float* ob = g_oscr + ((size_t)((n * 4 + h) * 100 + i * 10 + wid)) * 1024;
#pragma unroll
    for (int nt = 0; nt < 8; nt++) {
        float2 lo = make_float2(d2[nt][0] * rinv0, d2[nt][1] * rinv0);
        float2 hi = make_float2(d2[nt][2] * rinv1, d2[nt][3] * rinv1);
        *(float2*)&ob[(size_t)gid * 64 + nt * 8 + ctid * 2] = lo;
        *(float2*)&ob[(size_t)(gid + 8) * 64 + nt * 8 + ctid * 2] = hi;
    }
}

// ---------------------------------------------------------------------------
// Fold: block per (n, h, m-row). Reads contiguous [s][l-row][d] segments.
// ---------------------------------------------------------------------------
__global__ __launch_bounds__(256) void fold_kernel() {
    __shared__ float seg[2][10][256];
    const int bid = blockIdx.x;
    const int n = bid / 88;
    const int rem = bid - n * 88;
    const int h = rem / 22;
    const int m = rem - h * 22;

    int ia_min = (m - 3 + 1) >> 1; if (ia_min < 0) ia_min = 0;
    int ia_max = m >> 1;           if (ia_max > 9) ia_max = 9;
    const int nia = ia_max - ia_min + 1;   // 1 or 2

    const int tid = threadIdx.x;
    const float* obase = g_oscr + ((size_t)(n * 4 + h) * 100) * 1024;
    for (int f = tid; f < nia * 2560; f += 256) {
        int a = f / 2560, r = f - a * 2560;
        int ib = r >> 8, off = r & 255;
        int ia = ia_min + a;
        int ja = m - 2 * ia;
        seg[a][ib][off] = obase[(size_t)(ia * 10 + ib) * 1024 + ja * 256 + off];
    }
    __syncthreads();

    const int d = tid >> 2, sub = tid & 3;
    float* dst = g_folded + ((size_t)(n * 256 + h * 64 + d)) * PACT + m * 22;
    for (int m2 = sub; m2 < 22; m2 += 4) {
        float acc = 0.f;
        int jb0 = m2 & 1;
#pragma unroll
        for (int jj = 0; jj < 2; jj++) {
            int jb = jb0 + jj * 2;
            int ib = (m2 - jb) >> 1;
            if (ib < 0 || ib > 9) continue;
            acc += seg[0][ib][jb * 64 + d];
            if (nia == 2) acc += seg[1][ib][jb * 64 + d];
        }
        dst[m2] = acc;
    }
}

// ---------------------------------------------------------------------------
// Writeout: full output = bias everywhere, gathered proj value at active px
// ---------------------------------------------------------------------------
__global__ __launch_bounds__(256) void writeout(float* __restrict__ out,
                                                const float* __restrict__ b_proj) {
    size_t i4 = (size_t)blockIdx.x * 256 + threadIdx.x;
    if (i4 >= 8388608u) return;
    int ww0 = (int)(i4 & 15) * 4;
    int hh  = (int)(i4 >> 4) & 63;
    int c   = (int)(i4 >> 10) & 255;
    int n   = (int)(i4 >> 18);
    float bv = b_proj[c];
    float4 r = make_float4(bv, bv, bv, bv);
    if (hh % 3 == 0) {
        const float* pr = g_pout + ((size_t)(n * 256 + c)) * PACT + (hh / 3) * 22;
        if ((ww0 + 0) % 3 == 0) r.x = pr[(ww0 + 0) / 3];
        if ((ww0 + 1) % 3 == 0) r.y = pr[(ww0 + 1) / 3];
        if ((ww0 + 2) % 3 == 0) r.z = pr[(ww0 + 2) / 3];
        if ((ww0 + 3) % 3 == 0) r.w = pr[(ww0 + 3) / 3];
    }
    ((float4*)out)[i4] = r;
}

extern "C" void kernel_launch(void* const* d_in, const int* in_sizes, int n_in,
                              void* d_out, int out_size) {
    const float* q      = (const float*)d_in[0];
    const float* w_q    = (const float*)d_in[1];
    const float* b_q    = (const float*)d_in[2];
    const float* w_kv   = (const float*)d_in[3];
    const float* b_kv   = (const float*)d_in[4];
    const float* w_proj = (const float*)d_in[5];
    const float* b_proj = (const float*)d_in[6];
    float* out = (float*)d_out;

    prep_kernel<<<260, 256>>>(w_q, b_q, w_kv, b_kv, w_proj);
    pack_q<<<dim3(2, 32, NB), 256>>>(q);
    gemm_qkv_tc<<<dim3(4, 6, NB), 256>>>();
    attn_kernel<<<dim3(10, 4, NB), 320>>>();
    fold_kernel<<<dim3(NB * 4 * 22), 256>>>();
    gemm_proj_tc<<<dim3(4, 2, NB), 256>>>(b_proj);
    writeout<<<32768, 256>>>(out, b_proj);
}